// round 2
// baseline (speedup 1.0000x reference)
#include <cuda_runtime.h>
#include <cuda_bf16.h>
#include <cstdint>

// Problem dims (fixed by the dataset)
#define B_DIM 4096
#define D_DIM 1024
#define H1_DIM 128
#define H2_DIM 64
#define O_DIM 2

// Scratch (no cudaMalloc allowed)
__device__ float g_h1[B_DIM * H1_DIM];   // relu(x @ W1^T + b1), row-major [B][128]
__device__ float g_pr0[B_DIM * H1_DIM];  // kNN-averaged h1, row-major
__device__ float g_pr1[B_DIM * H1_DIM];  // relu(pr0 @ Wpr^T + bpr)
__device__ float g_h2[B_DIM * H2_DIM];   // relu(pr1 @ W2^T + b2)

// ---------------------------------------------------------------------------
// Generic tiled SGEMM: C[M,N] = act(A[M,K] @ B[N,K]^T + bias[N])
// BN must equal N (single column block). 256 threads. Thread tile RPTx8.
// ---------------------------------------------------------------------------
template <int BM, int BN, bool RELU>
__global__ __launch_bounds__(256) void gemm_bias_kernel(
    const float* __restrict__ A, const float* __restrict__ Bm,
    const float* __restrict__ bias, float* __restrict__ C,
    int M, int N, int K)
{
    constexpr int BK = 16;
    constexpr int NG = BN / 8;     // column groups of 8
    constexpr int RG = 256 / NG;   // row groups
    constexpr int RPT = BM / RG;   // rows per thread
    static_assert(BM % RG == 0, "tile mismatch");

    __shared__ float As[BM][BK + 1];      // [row][k], +1 pad
    __shared__ float Bs[BK][BN + 4];      // [k][col], +4 pad keeps float4 alignment

    const int tid = threadIdx.x;
    const int tx = tid % NG;              // column group
    const int ty = tid / NG;              // row group
    const int row0 = blockIdx.x * BM;

    float acc[RPT][8];
#pragma unroll
    for (int i = 0; i < RPT; i++)
#pragma unroll
        for (int j = 0; j < 8; j++) acc[i][j] = 0.0f;

    for (int k0 = 0; k0 < K; k0 += BK) {
        // Load A tile (BM x BK), consecutive lanes -> consecutive k (coalesced)
#pragma unroll
        for (int idx = tid; idx < BM * BK; idx += 256) {
            int r = idx / BK, kk = idx % BK;
            As[r][kk] = A[(size_t)(row0 + r) * K + k0 + kk];
        }
        // Load B tile transposed into [k][col]
#pragma unroll
        for (int idx = tid; idx < BN * BK; idx += 256) {
            int f = idx / BK, kk = idx % BK;
            Bs[kk][f] = Bm[(size_t)f * K + k0 + kk];
        }
        __syncthreads();

#pragma unroll
        for (int kk = 0; kk < BK; kk++) {
            float4 b0 = *reinterpret_cast<const float4*>(&Bs[kk][tx * 8]);
            float4 b1 = *reinterpret_cast<const float4*>(&Bs[kk][tx * 8 + 4]);
            float bv[8] = {b0.x, b0.y, b0.z, b0.w, b1.x, b1.y, b1.z, b1.w};
#pragma unroll
            for (int i = 0; i < RPT; i++) {
                float a = As[ty * RPT + i][kk];
#pragma unroll
                for (int j = 0; j < 8; j++)
                    acc[i][j] = fmaf(a, bv[j], acc[i][j]);
            }
        }
        __syncthreads();
    }

    // Epilogue: bias + optional ReLU, coalesced-ish float stores
#pragma unroll
    for (int i = 0; i < RPT; i++) {
        int r = row0 + ty * RPT + i;
#pragma unroll
        for (int j = 0; j < 8; j++) {
            int c = tx * 8 + j;
            float v = acc[i][j] + bias[c];
            if (RELU) v = fmaxf(v, 0.0f);
            C[(size_t)r * N + c] = v;
        }
    }
}

// ---------------------------------------------------------------------------
// Per-feature 6-NN batch averaging.
// One CTA per feature column (128 CTAs, 1024 threads).
// Pack (float bits << 16) | index into u64 (values are >=0 post-ReLU, so IEEE
// bits are order-monotonic), bitonic-sort 4096 keys in shared memory, then a
// greedy 5-step frontier walk gives each element the mean of its 6 nearest
// values (self included). Scatter results back by original index.
// ---------------------------------------------------------------------------
__global__ __launch_bounds__(1024) void knn_mean_kernel(
    const float* __restrict__ h1, float* __restrict__ out)
{
    __shared__ unsigned long long keys[B_DIM];  // 32 KB

    const int f = blockIdx.x;
    const int tid = threadIdx.x;

    for (int b = tid; b < B_DIM; b += 1024) {
        float v = h1[(size_t)b * H1_DIM + f];         // strided read, L2-served
        unsigned int bits = __float_as_uint(v);       // v >= 0 -> monotonic
        keys[b] = ((unsigned long long)bits << 16) | (unsigned)b;
    }
    __syncthreads();

    // Bitonic sort ascending, 4096 keys
    for (int k = 2; k <= B_DIM; k <<= 1) {
        for (int j = k >> 1; j > 0; j >>= 1) {
#pragma unroll 4
            for (int i = tid; i < B_DIM; i += 1024) {
                int ixj = i ^ j;
                if (ixj > i) {
                    unsigned long long a = keys[i];
                    unsigned long long b = keys[ixj];
                    bool up = (i & k) == 0;
                    if (up ? (a > b) : (a < b)) {
                        keys[i] = b;
                        keys[ixj] = a;
                    }
                }
            }
            __syncthreads();
        }
    }

    const float BIG = __int_as_float(0x7f000000);  // huge finite sentinel

    // Greedy 6-NN window + mean, scatter by original index
    for (int p = tid; p < B_DIM; p += 1024) {
        unsigned long long kp = keys[p];
        float v = __uint_as_float((unsigned int)(kp >> 16));
        int orig = (int)(kp & 0xFFFFu);
        float sum = v;
        int l = p - 1, r = p + 1;
#pragma unroll
        for (int s = 0; s < 5; s++) {
            float vl = (l >= 0)    ? __uint_as_float((unsigned int)(keys[l] >> 16)) : 0.0f;
            float vr = (r < B_DIM) ? __uint_as_float((unsigned int)(keys[r] >> 16)) : 0.0f;
            float dl = (l >= 0)    ? (v - vl) : BIG;
            float dr = (r < B_DIM) ? (vr - v) : BIG;
            if (dl <= dr) { sum += vl; l--; }
            else          { sum += vr; r++; }
        }
        out[(size_t)orig * H1_DIM + f] = sum * (1.0f / 6.0f);
    }
}

// ---------------------------------------------------------------------------
// Final tiny GEMM: out[B,2] = h2[B,64] @ Wo[2,64]^T + bo
// ---------------------------------------------------------------------------
__global__ __launch_bounds__(256) void final_kernel(
    const float* __restrict__ h2, const float* __restrict__ Wo,
    const float* __restrict__ bo, float* __restrict__ out)
{
    __shared__ float w[O_DIM * H2_DIM];
    __shared__ float bsh[O_DIM];
    if (threadIdx.x < O_DIM * H2_DIM) w[threadIdx.x] = Wo[threadIdx.x];
    if (threadIdx.x < O_DIM) bsh[threadIdx.x] = bo[threadIdx.x];
    __syncthreads();

    int b = blockIdx.x * blockDim.x + threadIdx.x;
    if (b >= B_DIM) return;
    const float* row = h2 + (size_t)b * H2_DIM;
    float s0 = 0.0f, s1 = 0.0f;
#pragma unroll
    for (int k = 0; k < H2_DIM; k++) {
        float x = row[k];
        s0 = fmaf(x, w[k], s0);
        s1 = fmaf(x, w[H2_DIM + k], s1);
    }
    out[(size_t)b * O_DIM + 0] = s0 + bsh[0];
    out[(size_t)b * O_DIM + 1] = s1 + bsh[1];
}

// ---------------------------------------------------------------------------
extern "C" void kernel_launch(void* const* d_in, const int* in_sizes, int n_in,
                              void* d_out, int out_size)
{
    const float* x   = (const float*)d_in[0];   // [4096,1024]
    const float* W1  = (const float*)d_in[1];   // [128,1024]
    const float* b1  = (const float*)d_in[2];   // [128]
    const float* Wpr = (const float*)d_in[3];   // [128,128]
    const float* bpr = (const float*)d_in[4];   // [128]
    const float* W2  = (const float*)d_in[5];   // [64,128]
    const float* b2  = (const float*)d_in[6];   // [64]
    const float* Wo  = (const float*)d_in[7];   // [2,64]
    const float* bo  = (const float*)d_in[8];   // [2]
    float* out = (float*)d_out;

    float *h1, *pr0, *pr1, *h2;
    cudaGetSymbolAddress((void**)&h1,  g_h1);
    cudaGetSymbolAddress((void**)&pr0, g_pr0);
    cudaGetSymbolAddress((void**)&pr1, g_pr1);
    cudaGetSymbolAddress((void**)&h2,  g_h2);

    // 1) h1 = relu(x @ W1^T + b1)           [4096,128], K=1024
    gemm_bias_kernel<32, 128, true><<<B_DIM / 32, 256>>>(x, W1, b1, h1,
                                                         B_DIM, H1_DIM, D_DIM);
    // 2) pr0 = per-feature 6-NN mean of h1  [4096,128]
    knn_mean_kernel<<<H1_DIM, 1024>>>(h1, pr0);
    // 3) pr1 = relu(pr0 @ Wpr^T + bpr)      [4096,128], K=128
    gemm_bias_kernel<32, 128, true><<<B_DIM / 32, 256>>>(pr0, Wpr, bpr, pr1,
                                                         B_DIM, H1_DIM, H1_DIM);
    // 4) h2 = relu(pr1 @ W2^T + b2)         [4096,64], K=128
    gemm_bias_kernel<32, 64, true><<<B_DIM / 32, 256>>>(pr1, W2, b2, h2,
                                                        B_DIM, H2_DIM, H1_DIM);
    // 5) out = h2 @ Wo^T + bo               [4096,2]
    final_kernel<<<(B_DIM + 255) / 256, 256>>>(h2, Wo, bo, out);
}

// round 3
// speedup vs baseline: 1.4883x; 1.4883x over previous
#include <cuda_runtime.h>
#include <cuda_bf16.h>
#include <cstdint>

#define B_DIM 4096
#define D_DIM 1024
#define H1_DIM 128
#define H2_DIM 64
#define O_DIM 2

// Scratch (no cudaMalloc allowed)
__device__ float g_h1[B_DIM * H1_DIM];
__device__ float g_pr0[B_DIM * H1_DIM];
__device__ float g_pr1[B_DIM * H1_DIM];

// ---------------------------------------------------------------------------
// Packed fp32x2 helpers (Blackwell FFMA2 — only reachable via PTX)
// ---------------------------------------------------------------------------
__device__ __forceinline__ unsigned long long pk2(float x, float y) {
    unsigned long long r;
    asm("mov.b64 %0, {%1, %2};" : "=l"(r) : "f"(x), "f"(y));
    return r;
}
__device__ __forceinline__ void ffma2(unsigned long long& d,
                                      unsigned long long a,
                                      unsigned long long b) {
    asm("fma.rn.f32x2 %0, %1, %2, %0;" : "+l"(d) : "l"(a), "l"(b));
}
__device__ __forceinline__ float2 upk2(unsigned long long v) {
    float2 f;
    asm("mov.b64 {%0, %1}, %2;" : "=f"(f.x), "=f"(f.y) : "l"(v));
    return f;
}

// ---------------------------------------------------------------------------
// Pipelined SGEMM with FFMA2: C[M,N] = act(A[M,K] @ B[N,K]^T + bias)
// BM=32, BN=64, BK=32, 128 threads. grid = (M/32, N/64).
// Each thread: 2 rows x 8 cols (cols {tx*4..+3} and {32+tx*4..+3}).
// ---------------------------------------------------------------------------
template <bool RELU>
__global__ __launch_bounds__(128) void gemm_f2_kernel(
    const float* __restrict__ A, const float* __restrict__ Bm,
    const float* __restrict__ bias, float* __restrict__ C,
    int M, int N, int K)
{
    constexpr int BM = 32, BN = 64, BK = 32;
    constexpr int BS_STRIDE = 68;  // 16B-aligned LDS.128 reads, bank-clean

    __shared__ float As[BM][BK + 1];
    __shared__ float Bs[BK][BS_STRIDE];

    const int tid = threadIdx.x;
    const int tx = tid & 7;        // 8 col groups
    const int ty = tid >> 3;       // 16 row groups -> rows ty*2, ty*2+1
    const int row0 = blockIdx.x * BM;
    const int col0 = blockIdx.y * BN;

    const float* Bp = Bm + (size_t)col0 * K;

    // ldg thread mapping: kq = tid&7 (float4 along K), r/f = tid>>3 (+16*it)
    const int l_kq = tid & 7;
    const int l_r  = tid >> 3;

    unsigned long long acc[2][4];
#pragma unroll
    for (int i = 0; i < 2; i++)
#pragma unroll
        for (int j = 0; j < 4; j++) acc[i][j] = 0ull;

    const int NB = K / BK;
    float4 pa[2], pb[4];

    // prefetch block 0
#pragma unroll
    for (int it = 0; it < 2; it++)
        pa[it] = *(const float4*)&A[(size_t)(row0 + l_r + it * 16) * K + l_kq * 4];
#pragma unroll
    for (int it = 0; it < 4; it++)
        pb[it] = *(const float4*)&Bp[(size_t)(l_r + it * 16) * K + l_kq * 4];

    // store block 0
#pragma unroll
    for (int it = 0; it < 2; it++) {
        int r = l_r + it * 16;
        As[r][l_kq * 4 + 0] = pa[it].x; As[r][l_kq * 4 + 1] = pa[it].y;
        As[r][l_kq * 4 + 2] = pa[it].z; As[r][l_kq * 4 + 3] = pa[it].w;
    }
#pragma unroll
    for (int it = 0; it < 4; it++) {
        int f = l_r + it * 16;
        Bs[l_kq * 4 + 0][f] = pb[it].x; Bs[l_kq * 4 + 1][f] = pb[it].y;
        Bs[l_kq * 4 + 2][f] = pb[it].z; Bs[l_kq * 4 + 3][f] = pb[it].w;
    }
    __syncthreads();

    const int ty2 = ty * 2;
    for (int kb = 0; kb < NB; kb++) {
        const bool more = (kb + 1 < NB);
        if (more) {
            const int k0 = (kb + 1) * BK;
#pragma unroll
            for (int it = 0; it < 2; it++)
                pa[it] = *(const float4*)&A[(size_t)(row0 + l_r + it * 16) * K + k0 + l_kq * 4];
#pragma unroll
            for (int it = 0; it < 4; it++)
                pb[it] = *(const float4*)&Bp[(size_t)(l_r + it * 16) * K + k0 + l_kq * 4];
        }

#pragma unroll
        for (int kk = 0; kk < BK; kk++) {
            float a0 = As[ty2][kk];
            float a1 = As[ty2 + 1][kk];
            unsigned long long ap0 = pk2(a0, a0);
            unsigned long long ap1 = pk2(a1, a1);
            ulonglong2 b01 = *(const ulonglong2*)&Bs[kk][tx * 4];
            ulonglong2 b23 = *(const ulonglong2*)&Bs[kk][32 + tx * 4];
            ffma2(acc[0][0], ap0, b01.x); ffma2(acc[0][1], ap0, b01.y);
            ffma2(acc[0][2], ap0, b23.x); ffma2(acc[0][3], ap0, b23.y);
            ffma2(acc[1][0], ap1, b01.x); ffma2(acc[1][1], ap1, b01.y);
            ffma2(acc[1][2], ap1, b23.x); ffma2(acc[1][3], ap1, b23.y);
        }
        __syncthreads();
        if (more) {
#pragma unroll
            for (int it = 0; it < 2; it++) {
                int r = l_r + it * 16;
                As[r][l_kq * 4 + 0] = pa[it].x; As[r][l_kq * 4 + 1] = pa[it].y;
                As[r][l_kq * 4 + 2] = pa[it].z; As[r][l_kq * 4 + 3] = pa[it].w;
            }
#pragma unroll
            for (int it = 0; it < 4; it++) {
                int f = l_r + it * 16;
                Bs[l_kq * 4 + 0][f] = pb[it].x; Bs[l_kq * 4 + 1][f] = pb[it].y;
                Bs[l_kq * 4 + 2][f] = pb[it].z; Bs[l_kq * 4 + 3][f] = pb[it].w;
            }
            __syncthreads();
        }
    }

    // Epilogue: bias + ReLU, float4 stores
#pragma unroll
    for (int i = 0; i < 2; i++) {
        const int r = row0 + ty2 + i;
#pragma unroll
        for (int half = 0; half < 2; half++) {
            const int c = half * 32 + tx * 4;
            float2 p0 = upk2(acc[i][half * 2 + 0]);
            float2 p1 = upk2(acc[i][half * 2 + 1]);
            float4 v;
            v.x = p0.x + bias[col0 + c + 0];
            v.y = p0.y + bias[col0 + c + 1];
            v.z = p1.x + bias[col0 + c + 2];
            v.w = p1.y + bias[col0 + c + 3];
            if (RELU) {
                v.x = fmaxf(v.x, 0.0f); v.y = fmaxf(v.y, 0.0f);
                v.z = fmaxf(v.z, 0.0f); v.w = fmaxf(v.w, 0.0f);
            }
            *(float4*)&C[(size_t)r * N + col0 + c] = v;
        }
    }
}

// ---------------------------------------------------------------------------
// Per-feature 6-NN batch averaging. One CTA per feature (128 CTAs, 1024 thr).
// Bitonic sort of packed (value_bits<<16 | index) keys, then greedy 5-step
// frontier walk over the sorted order.
// ---------------------------------------------------------------------------
__global__ __launch_bounds__(1024) void knn_mean_kernel(
    const float* __restrict__ h1, float* __restrict__ out)
{
    __shared__ unsigned long long keys[B_DIM];  // 32 KB

    const int f = blockIdx.x;
    const int tid = threadIdx.x;

#pragma unroll
    for (int b = tid; b < B_DIM; b += 1024) {
        float v = h1[(size_t)b * H1_DIM + f];
        unsigned int bits = __float_as_uint(v);   // v >= 0 -> order-monotonic
        keys[b] = ((unsigned long long)bits << 16) | (unsigned)b;
    }
    __syncthreads();

    // Bitonic sort, exact pair indexing: 2 compare-exchanges per thread/phase
    for (int k = 2; k <= B_DIM; k <<= 1) {
        for (int j = k >> 1; j > 0; j >>= 1) {
#pragma unroll 2
            for (int p = tid; p < B_DIM / 2; p += 1024) {
                int i = ((p & ~(j - 1)) << 1) | (p & (j - 1));
                int ixj = i | j;
                unsigned long long a = keys[i];
                unsigned long long b = keys[ixj];
                bool up = (i & k) == 0;
                if (up ? (a > b) : (a < b)) {
                    keys[i] = b;
                    keys[ixj] = a;
                }
            }
            __syncthreads();
        }
    }

    const float BIG = __int_as_float(0x7f000000);

#pragma unroll
    for (int p = tid; p < B_DIM; p += 1024) {
        unsigned long long kp = keys[p];
        float v = __uint_as_float((unsigned int)(kp >> 16));
        int orig = (int)(kp & 0xFFFFu);
        float sum = v;
        int l = p - 1, r = p + 1;
#pragma unroll
        for (int s = 0; s < 5; s++) {
            float vl = (l >= 0)     ? __uint_as_float((unsigned int)(keys[l] >> 16)) : 0.0f;
            float vr = (r < B_DIM)  ? __uint_as_float((unsigned int)(keys[r] >> 16)) : 0.0f;
            float dl = (l >= 0)     ? (v - vl) : BIG;
            float dr = (r < B_DIM)  ? (vr - v) : BIG;
            if (dl <= dr) { sum += vl; l--; }
            else          { sum += vr; r++; }
        }
        out[(size_t)orig * H1_DIM + f] = sum * (1.0f / 6.0f);
    }
}

// ---------------------------------------------------------------------------
// Fused tail: h2 = relu(pr1 @ W2^T + b2); out = h2 @ Wo^T + bo
// 256 CTAs x 256 threads, 16 rows per CTA. W2/Wo resident in smem.
// ---------------------------------------------------------------------------
__global__ __launch_bounds__(256) void tail_kernel(
    const float* __restrict__ pr1, const float* __restrict__ W2,
    const float* __restrict__ b2, const float* __restrict__ Wo,
    const float* __restrict__ bo, float* __restrict__ out)
{
    constexpr int RT = 16;
    __shared__ float w2s[H2_DIM][H1_DIM + 4];   // 64 x 132 (33.8 KB)
    __shared__ float xs[RT][H1_DIM];            // 16 x 128 (8 KB)
    __shared__ float h2s[RT][H2_DIM + 2];       // 16 x 66
    __shared__ float wos[O_DIM][H2_DIM];
    __shared__ float bsh[H2_DIM + O_DIM];

    const int tid = threadIdx.x;
    const int r0 = blockIdx.x * RT;

    // W2 -> smem (stride 132 keeps float4 stores 16B-aligned: 132*4=528=33*16)
    for (int idx = tid; idx < H2_DIM * (H1_DIM / 4); idx += 256) {
        int c = idx >> 5, kq = idx & 31;
        *(float4*)&w2s[c][kq * 4] = *(const float4*)&W2[(size_t)c * H1_DIM + kq * 4];
    }
    for (int idx = tid; idx < RT * (H1_DIM / 4); idx += 256) {
        int r = idx >> 5, kq = idx & 31;
        *(float4*)&xs[r][kq * 4] = *(const float4*)&pr1[(size_t)(r0 + r) * H1_DIM + kq * 4];
    }
    if (tid < O_DIM * H2_DIM) wos[tid >> 6][tid & 63] = Wo[tid];
    if (tid < H2_DIM) bsh[tid] = b2[tid];
    if (tid < O_DIM) bsh[H2_DIM + tid] = bo[tid];
    __syncthreads();

    // Stage A: h2[16][64]
    const int tx = tid & 15, ty = tid >> 4;
    float acc[4] = {0.f, 0.f, 0.f, 0.f};
#pragma unroll
    for (int kq = 0; kq < H1_DIM / 4; kq++) {
        float4 a = *(const float4*)&xs[ty][kq * 4];
#pragma unroll
        for (int j = 0; j < 4; j++) {
            float4 w = *(const float4*)&w2s[tx * 4 + j][kq * 4];
            acc[j] = fmaf(a.x, w.x, acc[j]);
            acc[j] = fmaf(a.y, w.y, acc[j]);
            acc[j] = fmaf(a.z, w.z, acc[j]);
            acc[j] = fmaf(a.w, w.w, acc[j]);
        }
    }
#pragma unroll
    for (int j = 0; j < 4; j++) {
        int c = tx * 4 + j;
        h2s[ty][c] = fmaxf(acc[j] + bsh[c], 0.0f);
    }
    __syncthreads();

    // Stage B: out[16][2]
    if (tid < RT * O_DIM) {
        int r = tid >> 1, o = tid & 1;
        float s = 0.0f;
#pragma unroll
        for (int k = 0; k < H2_DIM; k++)
            s = fmaf(h2s[r][k], wos[o][k], s);
        out[(size_t)(r0 + r) * O_DIM + o] = s + bsh[H2_DIM + o];
    }
}

// ---------------------------------------------------------------------------
extern "C" void kernel_launch(void* const* d_in, const int* in_sizes, int n_in,
                              void* d_out, int out_size)
{
    const float* x   = (const float*)d_in[0];
    const float* W1  = (const float*)d_in[1];
    const float* b1  = (const float*)d_in[2];
    const float* Wpr = (const float*)d_in[3];
    const float* bpr = (const float*)d_in[4];
    const float* W2  = (const float*)d_in[5];
    const float* b2  = (const float*)d_in[6];
    const float* Wo  = (const float*)d_in[7];
    const float* bo  = (const float*)d_in[8];
    float* out = (float*)d_out;

    float *h1, *pr0, *pr1;
    cudaGetSymbolAddress((void**)&h1,  g_h1);
    cudaGetSymbolAddress((void**)&pr0, g_pr0);
    cudaGetSymbolAddress((void**)&pr1, g_pr1);

    // 1) h1 = relu(x @ W1^T + b1)        [4096,128], K=1024, 256 CTAs
    gemm_f2_kernel<true><<<dim3(B_DIM / 32, H1_DIM / 64), 128>>>(
        x, W1, b1, h1, B_DIM, H1_DIM, D_DIM);
    // 2) pr0 = per-feature 6-NN mean
    knn_mean_kernel<<<H1_DIM, 1024>>>(h1, pr0);
    // 3) pr1 = relu(pr0 @ Wpr^T + bpr)   [4096,128], K=128, 256 CTAs
    gemm_f2_kernel<true><<<dim3(B_DIM / 32, H1_DIM / 64), 128>>>(
        pr0, Wpr, bpr, pr1, B_DIM, H1_DIM, H1_DIM);
    // 4+5) h2 + out fused
    tail_kernel<<<B_DIM / 16, 256>>>(pr1, W2, b2, Wo, bo, out);
}